// round 16
// baseline (speedup 1.0000x reference)
#include <cuda_runtime.h>
#include <cstdint>
#include <math.h>

#define NBINS 256
#define TILE_PIXELS 16384   // 128*128
#define MAXC 32
#define NPART 1184          // k_reduce grid (one full wave at 8 blocks/SM)
#define HIST_GRID 888       // one full wave at 6 blocks/SM
#define OUT_GRID 1184       // one full wave at 8 blocks/SM

struct Params {
    float c1, c2;          // x01 = v*c1 + c2
    float c1b, c2b;        // d_f = v*c1b + c2b = x01*256 - win_lo (+1e-5 bias)
    float c1c, c2c;        // lb_f = v*c1c + c2c = x01*255
    float dhi;             // upper clamp for d_f: 255-win_lo
    float maxval;
    int flag, win_lo;
};

__device__ Params   g_par;
__device__ double   g_psum[NPART];
__device__ double   g_psq[NPART];
__device__ float    g_pmn[NPART];
__device__ float    g_pmx[NPART];
__device__ unsigned g_tile_h;                          // hist work-steal ticket
__device__ unsigned g_tile_o;                          // out  work-steal ticket
__device__ float    g_lut[MAXC * 64 * NBINS];          // 2 MB
__device__ uint2    g_tblq[MAXC * 81 * NBINS];         // 5.3 MB bf16-packed (a0,b0,a1,b1)
__device__ unsigned g_bins[(MAXC << 20) >> 2];         // 32 MB packed u8 lookup bins

// ---------------------------------------------------------------- reduce: deterministic per-block partials
__global__ void __launch_bounds__(256) k_reduce(const float4* __restrict__ x, int n16) {
    double s = 0.0, q = 0.0;
    float mn = 3.4e38f, mx = -3.4e38f;
    int stride = gridDim.x * blockDim.x;
    int half = n16 >> 1;                    // n16 is even (n = 2^25)
    for (int i = blockIdx.x * blockDim.x + threadIdx.x; i < half; i += stride) {
        const float4* p0 = x + (size_t)i * 4;
        const float4* p1 = x + (size_t)(i + half) * 4;
        float4 regs[8] = { p0[0], p0[1], p0[2], p0[3], p1[0], p1[1], p1[2], p1[3] };
        float fs = 0.0f, fq = 0.0f;
#pragma unroll
        for (int g = 0; g < 8; g++) {
            float4 v = regs[g];
            fs += v.x; fq = fmaf(v.x, v.x, fq); mn = fminf(mn, v.x); mx = fmaxf(mx, v.x);
            fs += v.y; fq = fmaf(v.y, v.y, fq); mn = fminf(mn, v.y); mx = fmaxf(mx, v.y);
            fs += v.z; fq = fmaf(v.z, v.z, fq); mn = fminf(mn, v.z); mx = fmaxf(mx, v.z);
            fs += v.w; fq = fmaf(v.w, v.w, fq); mn = fminf(mn, v.w); mx = fmaxf(mx, v.w);
        }
        s += (double)fs; q += (double)fq;
    }
#pragma unroll
    for (int o = 16; o; o >>= 1) {
        s  += __shfl_down_sync(0xffffffffu, s, o);
        q  += __shfl_down_sync(0xffffffffu, q, o);
        mn = fminf(mn, __shfl_down_sync(0xffffffffu, mn, o));
        mx = fmaxf(mx, __shfl_down_sync(0xffffffffu, mx, o));
    }
    __shared__ double ss[8], sq[8];
    __shared__ float  smn[8], smx[8];
    int w = threadIdx.x >> 5, l = threadIdx.x & 31;
    if (l == 0) { ss[w] = s; sq[w] = q; smn[w] = mn; smx[w] = mx; }
    __syncthreads();
    if (w == 0) {
        s  = (l < 8) ? ss[l]  : 0.0;
        q  = (l < 8) ? sq[l]  : 0.0;
        mn = (l < 8) ? smn[l] : 3.4e38f;
        mx = (l < 8) ? smx[l] : -3.4e38f;
#pragma unroll
        for (int o = 4; o; o >>= 1) {
            s  += __shfl_down_sync(0xffffffffu, s, o);
            q  += __shfl_down_sync(0xffffffffu, q, o);
            mn = fminf(mn, __shfl_down_sync(0xffffffffu, mn, o));
            mx = fmaxf(mx, __shfl_down_sync(0xffffffffu, mx, o));
        }
        if (l == 0) {
            g_psum[blockIdx.x] = s;
            g_psq[blockIdx.x]  = q;
            g_pmn[blockIdx.x]  = mn;
            g_pmx[blockIdx.x]  = mx;
        }
    }
}

// ---------------------------------------------------------------- finalize: reduce partials + derive params
// Also resets the work-steal tickets (runs before hist/out in stream order).
__global__ void __launch_bounds__(256) k_finalize(int n) {
    int t = threadIdx.x;
    double s = 0.0, q = 0.0;
    float mn = 3.4e38f, mx = -3.4e38f;
    for (int i = t; i < NPART; i += 256) {
        s += g_psum[i]; q += g_psq[i];
        mn = fminf(mn, g_pmn[i]); mx = fmaxf(mx, g_pmx[i]);
    }
#pragma unroll
    for (int o = 16; o; o >>= 1) {
        s  += __shfl_down_sync(0xffffffffu, s, o);
        q  += __shfl_down_sync(0xffffffffu, q, o);
        mn = fminf(mn, __shfl_down_sync(0xffffffffu, mn, o));
        mx = fmaxf(mx, __shfl_down_sync(0xffffffffu, mx, o));
    }
    __shared__ double ss[8], sq[8];
    __shared__ float  smn[8], smx[8];
    int w = t >> 5, l = t & 31;
    if (l == 0) { ss[w] = s; sq[w] = q; smn[w] = mn; smx[w] = mx; }
    __syncthreads();
    if (t == 0) {
        for (int k = 1; k < 8; k++) {
            ss[0] += ss[k]; sq[0] += sq[k];
            smn[0] = fminf(smn[0], smn[k]); smx[0] = fmaxf(smx[0], smx[k]);
        }
        double dn = (double)n;
        double var = (sq[0] - ss[0] * ss[0] / dn) / (dn - 1.0);
        double sd = sqrt(var);
        float xminf = smn[0], xmaxf = smx[0];
        double range = (double)xmaxf - (double)xminf;
        double ct = sd / range;                 // std(x01) == std(x)/range
        int flag = (ct < 0.05) ? 1 : 0;
        double beta = 10.0 * ct;
        double cl = 1.0 / (1.0 - beta) + beta;
        double mv = floor(cl * (double)TILE_PIXELS / (double)NBINS);
        if (mv < 1.0) mv = 1.0;
        Params p;
        p.c1 = (float)(1.0 / range);
        p.c2 = (float)(-(double)xminf / range);
        int hot = (int)(p.c2 * 256.0f);
        int wl = hot - 4;
        wl = wl < 0 ? 0 : (wl > 248 ? 248 : wl);
        p.win_lo = wl;
        p.c1b = (float)(256.0 / range);
        // +1e-5 bias guarantees df > -wl strictly so the lower clamp can be
        // dropped in the hot loop (1e-5-bin boundary shift, negligible).
        p.c2b = (float)(-(double)xminf * 256.0 / range - (double)wl + 1e-5);
        p.c1c = (float)(255.0 / range);
        p.c2c = (float)(-(double)xminf * 255.0 / range);
        p.dhi = (float)(255 - wl);
        p.maxval = (float)mv;
        p.flag = flag;
        g_par = p;
        g_tile_h = 0u;                       // reset work-steal tickets
        g_tile_o = 0u;
    }
}

// ---------------------------------------------------------------- per-tile histogram + LUT (persistent)
// One full wave (888 blocks @ 6/SM); tiles grabbed via atomic ticket in
// REVERSE order (L2-tail reuse from k_reduce). Eliminates wave quantization.
__global__ void __launch_bounds__(256, 6) k_hist_lut(const float4* __restrict__ x, int ntiles) {
    __shared__ unsigned shw[8 * NBINS];   // 8KB per-warp u32 histograms
    __shared__ float red[40];
    __shared__ int s_tile;
    Params p = g_par;
    if (!p.flag) return;
    int t = threadIdx.x;
    int wid = t >> 5, lane = t & 31;
    unsigned* myh = shw + (wid << 8);
    float c1b = p.c1b, c2b = p.c2b, c1c = p.c1c, c2c = p.c2c;
    float dhi = p.dhi;
    int win_lo = p.win_lo;

    for (;;) {
        __syncthreads();                   // all warps done with previous tile's shw/red
        if (t == 0) s_tile = ntiles - 1 - (int)atomicAdd(&g_tile_h, 1u);
        // zero 8KB
        {
            uint4 zz; zz.x = 0u; zz.y = 0u; zz.z = 0u; zz.w = 0u;
            ((uint4*)shw)[t] = zz;
            ((uint4*)shw)[256 + t] = zz;
        }
        __syncthreads();
        int bid = s_tile;
        if (bid < 0) return;
        int c = bid >> 6, gy = (bid >> 3) & 7, gx = bid & 7;

        int base = c * 262144 + (gy * 128) * 256 + gx * 32;   // float4 index of tile origin
        int g0 = base + (wid << 8) + lane;                    // this thread's first float4
        unsigned nib = 0u;                                    // 8 nibble counters
        unsigned accA = 0u, accB = 0u;                        // u8-field accumulators

        float4 v0 = x[g0];
        float4 v1 = x[g0 + 1 * 2048];
        float4 v2 = x[g0 + 2 * 2048];
        float4 v3 = x[g0 + 3 * 2048];

#pragma unroll
        for (int it = 0; it < 16; it++) {
            float4 cur = v0; v0 = v1; v1 = v2; v2 = v3;
            if (it + 4 < 16) v3 = x[g0 + (it + 4) * 2048];
            float vals[4] = { cur.x, cur.y, cur.z, cur.w };
            int lbs[4];
#pragma unroll
            for (int j = 0; j < 4; j++) {
                float v = vals[j];
                float df = fminf(fmaf(v, c1b, c2b), dhi);   // lower clamp dropped (bias)
                int d = __float2int_rd(df);                 // window-relative bin (floor)
                lbs[j] = (int)fmaf(v, c1c, c2c);            // lookup bin (trunc; in [0,255])
                unsigned inc = __funnelshift_lc(0u, 1u, ((unsigned)d) << 2);
                nib += inc;
                if (inc == 0u) atomicAdd(&myh[d + win_lo], 1u);   // residue, rare
            }
            unsigned packed = __byte_perm(__byte_perm((unsigned)lbs[0], (unsigned)lbs[1], 0x0040),
                                          __byte_perm((unsigned)lbs[2], (unsigned)lbs[3], 0x0040),
                                          0x5410);
            g_bins[g0 + it * 2048] = packed;
            if (it & 1) {                                     // flush every 8 values
                accA += nib & 0x0F0F0F0Fu;
                accB += (nib >> 4) & 0x0F0F0F0Fu;
                nib = 0u;
            }
        }

        // ---- merge register windows
        unsigned pk0 =  accA        & 0x00FF00FFu;
        unsigned pk1 = (accA >> 8)  & 0x00FF00FFu;
        unsigned pk2 =  accB        & 0x00FF00FFu;
        unsigned pk3 = (accB >> 8)  & 0x00FF00FFu;
#pragma unroll
        for (int o = 16; o; o >>= 1) {
            pk0 += __shfl_down_sync(0xffffffffu, pk0, o);     // fields <= 2048
            pk1 += __shfl_down_sync(0xffffffffu, pk1, o);
            pk2 += __shfl_down_sync(0xffffffffu, pk2, o);
            pk3 += __shfl_down_sync(0xffffffffu, pk3, o);
        }
        if (lane == 0) {
            myh[win_lo + 0] = pk0 & 0xFFFFu;  myh[win_lo + 4] = pk0 >> 16;
            myh[win_lo + 2] = pk1 & 0xFFFFu;  myh[win_lo + 6] = pk1 >> 16;
            myh[win_lo + 1] = pk2 & 0xFFFFu;  myh[win_lo + 5] = pk2 >> 16;
            myh[win_lo + 3] = pk3 & 0xFFFFu;  myh[win_lo + 7] = pk3 >> 16;
        }
        __syncthreads();

        unsigned cnt = 0;
#pragma unroll
        for (int w = 0; w < 8; w++) cnt += shw[(w << 8) + t];

        float clipped = fminf((float)cnt, p.maxval);

        float s = clipped;
#pragma unroll
        for (int o = 16; o; o >>= 1) s += __shfl_down_sync(0xffffffffu, s, o);
        if (lane == 0) red[wid] = s;
        __syncthreads();
        if (t < 32) {
            float v2s = (t < 8) ? red[t] : 0.0f;
#pragma unroll
            for (int o = 4; o; o >>= 1) v2s += __shfl_down_sync(0xffffffffu, v2s, o);
            if (t == 0) red[32] = v2s;
        }
        __syncthreads();
        float total = red[32];
        int ex = TILE_PIXELS - (int)total;
        int residual = ex & (NBINS - 1);
        int redist = ex >> 8;
        float hv = clipped + (float)redist + ((t < residual) ? 1.0f : 0.0f);

        float vsc = hv;
#pragma unroll
        for (int o = 1; o < 32; o <<= 1) {
            float u = __shfl_up_sync(0xffffffffu, vsc, o);
            if (lane >= o) vsc += u;
        }
        if (lane == 31) red[wid] = vsc;
        __syncthreads();
        float off = 0.0f;
        for (int k = 0; k < wid; k++) off += red[k];
        vsc += off;

        float lutv = floorf(fminf(vsc * (255.0f / 16384.0f), 255.0f));
        g_lut[bid * NBINS + t] = lutv;
    }
}

// ---------------------------------------------------------------- bf16-packed bilinear table
__global__ void __launch_bounds__(128) k_tbl() {
    Params p = g_par;
    if (!p.flag) return;
    int b = blockIdx.x >> 1;                   // slice = c*9 + ry
    int bin = ((blockIdx.x & 1) << 7) + threadIdx.x;
    int c = b / 9, ry = b % 9;
    int y0 = max(ry - 1, 0); int y1 = min(y0 + 1, 7);
    const float* L = g_lut + c * 64 * NBINS;
    float r0[8], r1[8];
#pragma unroll
    for (int xx = 0; xx < 8; xx++) r0[xx] = L[(y0 * 8 + xx) * NBINS + bin];
#pragma unroll
    for (int xx = 0; xx < 8; xx++) r1[xx] = L[(y1 * 8 + xx) * NBINS + bin];
#pragma unroll
    for (int rx = 0; rx < 9; rx++) {
        int x0 = max(rx - 1, 0); int x1 = min(x0 + 1, 7);
        float a0 = r0[x0], b0 = r0[x1] - r0[x0];
        float a1 = r1[x0], b1 = r1[x1] - r1[x0];
        uint2 e;
        e.x = (__float_as_uint(b0) & 0xFFFF0000u) | (__float_as_uint(a0) >> 16);
        e.y = (__float_as_uint(b1) & 0xFFFF0000u) | (__float_as_uint(a1) >> 16);
        g_tblq[(b * 9 + rx) * NBINS + bin] = e;
    }
}

// ---------------------------------------------------------------- output (persistent): ONE 8B gather + interp + log2
// One full wave (1184 blocks @ 8/SM); chunks grabbed via atomic ticket.
__global__ void __launch_bounds__(256) k_out(const float4* __restrict__ x,
                                             float4* __restrict__ out, int n4, int nchunk) {
    Params p = g_par;
    int t = threadIdx.x;
    __shared__ int s_chunk;
    if (p.flag) {
        // per-thread invariants (independent of chunk's row position)
        int w4 = t << 2;
        int rx = (w4 + 64) >> 7;
        float wx0 = fmaf((float)w4, 0.0078125f, 0.50390625f - (float)rx);
        float wx1 = wx0 + 0.0078125f;
        float wx2 = wx0 + 0.015625f;
        float wx3 = wx0 + 0.0234375f;
        for (;;) {
            __syncthreads();
            if (t == 0) s_chunk = (int)atomicAdd(&g_tile_o, 1u);
            __syncthreads();
            int chunk = s_chunk;
            if (chunk >= nchunk) return;
            int i0 = chunk * 2048;
            int base = i0 + t;
            unsigned bp[8];
#pragma unroll
            for (int k = 0; k < 8; k++) bp[k] = __ldcs(&g_bins[base + k * 256]);
            int c  = i0 >> 18;
            int h0 = (i0 & 262143) >> 8;
            const uint2* tbc = g_tblq + (c * 81 + rx) * NBINS;
            float wx[4] = { wx0, wx1, wx2, wx3 };
#pragma unroll
            for (int k = 0; k < 8; k++) {
                int h  = h0 + k;
                int ry = (h + 64) >> 7;
                float wy = fmaf((float)h, 0.0078125f, 0.50390625f - (float)ry);
                const uint2* tb = tbc + ry * 9 * NBINS;
                float o[4];
#pragma unroll
                for (int j = 0; j < 4; j++) {
                    unsigned bin = __byte_perm(bp[k], 0u, 0x4440u + (unsigned)j);
                    uint2 e = tb[bin];
                    float a0 = __uint_as_float(e.x << 16);
                    float b0 = __uint_as_float(e.x & 0xFFFF0000u);
                    float a1 = __uint_as_float(e.y << 16);
                    float b1 = __uint_as_float(e.y & 0xFFFF0000u);
                    float top = fmaf(wx[j], b0, a0);
                    float bot = fmaf(wx[j], b1, a1);
                    float itp = fmaf(wy, bot - top, top);
                    float val = fmaf(itp, (1.0f / 255.0f), 1.0f);
                    o[j] = __log2f(val);
                }
                float4 ov; ov.x = o[0]; ov.y = o[1]; ov.z = o[2]; ov.w = o[3];
                __stcs(&out[base + k * 256], ov);
            }
        }
    } else {
        for (;;) {
            __syncthreads();
            if (t == 0) s_chunk = (int)atomicAdd(&g_tile_o, 1u);
            __syncthreads();
            int chunk = s_chunk;
            if (chunk >= nchunk) return;
            int base = chunk * 2048 + t;
#pragma unroll
            for (int k = 0; k < 8; k++) {
                int i = base + k * 256;
                if (i < n4) {
                    float4 v = x[i];
                    float4 ov;
                    ov.x = log2f(1.0f + fmaf(v.x, p.c1, p.c2));
                    ov.y = log2f(1.0f + fmaf(v.y, p.c1, p.c2));
                    ov.z = log2f(1.0f + fmaf(v.z, p.c1, p.c2));
                    ov.w = log2f(1.0f + fmaf(v.w, p.c1, p.c2));
                    __stcs(&out[i], ov);
                }
            }
        }
    }
}

// ---------------------------------------------------------------- launch
extern "C" void kernel_launch(void* const* d_in, const int* in_sizes, int n_in,
                              void* d_out, int out_size) {
    (void)n_in; (void)out_size;
    const float* x = (const float*)d_in[0];
    int n   = in_sizes[0];          // 32 * 1024 * 1024
    int C   = n >> 20;
    int n16 = n >> 4;
    int n4  = n >> 2;

    k_reduce<<<NPART, 256>>>((const float4*)x, n16);
    k_finalize<<<1, 256>>>(n);
    k_hist_lut<<<HIST_GRID, 256>>>((const float4*)x, C * 64);
    k_tbl<<<C * 9 * 2, 128>>>();
    k_out<<<OUT_GRID, 256>>>((const float4*)x, (float4*)d_out, n4, n4 / 2048);
}

// round 17
// speedup vs baseline: 1.0848x; 1.0848x over previous
#include <cuda_runtime.h>
#include <cstdint>
#include <math.h>

#define NBINS 256
#define TILE_PIXELS 16384   // 128*128
#define MAXC 32
#define NPART 1184          // k_reduce grid (one full wave at 8 blocks/SM)

struct Params {
    float c1, c2;          // x01 = v*c1 + c2
    float c1b, c2b;        // d_f = v*c1b + c2b = x01*256 - win_lo (+1e-5 bias)
    float c1c, c2c;        // lb_f = v*c1c + c2c = x01*255
    float dhi;             // upper clamp for d_f: 255-win_lo
    float maxval;
    int flag, win_lo;
};

__device__ Params   g_par;
__device__ double   g_psum[NPART];
__device__ double   g_psq[NPART];
__device__ float    g_pmn[NPART];
__device__ float    g_pmx[NPART];
__device__ float    g_lut[MAXC * 64 * NBINS];          // 2 MB
__device__ uint2    g_tblq[MAXC * 81 * NBINS];         // 5.3 MB bf16-packed (a0,b0,a1,b1)
__device__ unsigned g_bins[(MAXC << 20) >> 2];         // 32 MB packed u8 lookup bins

// ---------------------------------------------------------------- reduce: deterministic per-block partials
__global__ void __launch_bounds__(256) k_reduce(const float4* __restrict__ x, int n16) {
    double s = 0.0, q = 0.0;
    float mn = 3.4e38f, mx = -3.4e38f;
    int stride = gridDim.x * blockDim.x;
    int half = n16 >> 1;                    // n16 is even (n = 2^25)
    for (int i = blockIdx.x * blockDim.x + threadIdx.x; i < half; i += stride) {
        const float4* p0 = x + (size_t)i * 4;
        const float4* p1 = x + (size_t)(i + half) * 4;
        float4 regs[8] = { p0[0], p0[1], p0[2], p0[3], p1[0], p1[1], p1[2], p1[3] };
        float fs = 0.0f, fq = 0.0f;
#pragma unroll
        for (int g = 0; g < 8; g++) {
            float4 v = regs[g];
            fs += v.x; fq = fmaf(v.x, v.x, fq); mn = fminf(mn, v.x); mx = fmaxf(mx, v.x);
            fs += v.y; fq = fmaf(v.y, v.y, fq); mn = fminf(mn, v.y); mx = fmaxf(mx, v.y);
            fs += v.z; fq = fmaf(v.z, v.z, fq); mn = fminf(mn, v.z); mx = fmaxf(mx, v.z);
            fs += v.w; fq = fmaf(v.w, v.w, fq); mn = fminf(mn, v.w); mx = fmaxf(mx, v.w);
        }
        s += (double)fs; q += (double)fq;
    }
#pragma unroll
    for (int o = 16; o; o >>= 1) {
        s  += __shfl_down_sync(0xffffffffu, s, o);
        q  += __shfl_down_sync(0xffffffffu, q, o);
        mn = fminf(mn, __shfl_down_sync(0xffffffffu, mn, o));
        mx = fmaxf(mx, __shfl_down_sync(0xffffffffu, mx, o));
    }
    __shared__ double ss[8], sq[8];
    __shared__ float  smn[8], smx[8];
    int w = threadIdx.x >> 5, l = threadIdx.x & 31;
    if (l == 0) { ss[w] = s; sq[w] = q; smn[w] = mn; smx[w] = mx; }
    __syncthreads();
    if (w == 0) {
        s  = (l < 8) ? ss[l]  : 0.0;
        q  = (l < 8) ? sq[l]  : 0.0;
        mn = (l < 8) ? smn[l] : 3.4e38f;
        mx = (l < 8) ? smx[l] : -3.4e38f;
#pragma unroll
        for (int o = 4; o; o >>= 1) {
            s  += __shfl_down_sync(0xffffffffu, s, o);
            q  += __shfl_down_sync(0xffffffffu, q, o);
            mn = fminf(mn, __shfl_down_sync(0xffffffffu, mn, o));
            mx = fmaxf(mx, __shfl_down_sync(0xffffffffu, mx, o));
        }
        if (l == 0) {
            g_psum[blockIdx.x] = s;
            g_psq[blockIdx.x]  = q;
            g_pmn[blockIdx.x]  = mn;
            g_pmx[blockIdx.x]  = mx;
        }
    }
}

// ---------------------------------------------------------------- finalize: reduce partials + derive params
__global__ void __launch_bounds__(256) k_finalize(int n) {
    int t = threadIdx.x;
    double s = 0.0, q = 0.0;
    float mn = 3.4e38f, mx = -3.4e38f;
    for (int i = t; i < NPART; i += 256) {
        s += g_psum[i]; q += g_psq[i];
        mn = fminf(mn, g_pmn[i]); mx = fmaxf(mx, g_pmx[i]);
    }
#pragma unroll
    for (int o = 16; o; o >>= 1) {
        s  += __shfl_down_sync(0xffffffffu, s, o);
        q  += __shfl_down_sync(0xffffffffu, q, o);
        mn = fminf(mn, __shfl_down_sync(0xffffffffu, mn, o));
        mx = fmaxf(mx, __shfl_down_sync(0xffffffffu, mx, o));
    }
    __shared__ double ss[8], sq[8];
    __shared__ float  smn[8], smx[8];
    int w = t >> 5, l = t & 31;
    if (l == 0) { ss[w] = s; sq[w] = q; smn[w] = mn; smx[w] = mx; }
    __syncthreads();
    if (t == 0) {
        for (int k = 1; k < 8; k++) {
            ss[0] += ss[k]; sq[0] += sq[k];
            smn[0] = fminf(smn[0], smn[k]); smx[0] = fmaxf(smx[0], smx[k]);
        }
        double dn = (double)n;
        double var = (sq[0] - ss[0] * ss[0] / dn) / (dn - 1.0);
        double sd = sqrt(var);
        float xminf = smn[0], xmaxf = smx[0];
        double range = (double)xmaxf - (double)xminf;
        double ct = sd / range;                 // std(x01) == std(x)/range
        int flag = (ct < 0.05) ? 1 : 0;
        double beta = 10.0 * ct;
        double cl = 1.0 / (1.0 - beta) + beta;
        double mv = floor(cl * (double)TILE_PIXELS / (double)NBINS);
        if (mv < 1.0) mv = 1.0;
        Params p;
        p.c1 = (float)(1.0 / range);
        p.c2 = (float)(-(double)xminf / range);
        int hot = (int)(p.c2 * 256.0f);
        int wl = hot - 4;
        wl = wl < 0 ? 0 : (wl > 248 ? 248 : wl);
        p.win_lo = wl;
        p.c1b = (float)(256.0 / range);
        // +1e-5 bias guarantees df > -wl strictly so the lower clamp can be
        // dropped in the hot loop (1e-5-bin boundary shift, negligible).
        p.c2b = (float)(-(double)xminf * 256.0 / range - (double)wl + 1e-5);
        p.c1c = (float)(255.0 / range);
        p.c2c = (float)(-(double)xminf * 255.0 / range);
        p.dhi = (float)(255 - wl);
        p.maxval = (float)mv;
        p.flag = flag;
        g_par = p;
    }
}

// ---------------------------------------------------------------- per-tile histogram + LUT (fused)
// R9-measured-best config: depth-4 prefetch, 6 blocks/SM, static reversed grid.
__global__ void __launch_bounds__(256, 6) k_hist_lut(const float4* __restrict__ x) {
    __shared__ unsigned shw[8 * NBINS];   // 8KB per-warp u32 histograms
    __shared__ float red[40];
    Params p = g_par;
    if (!p.flag) return;
    int t = threadIdx.x;
    int bid = (int)gridDim.x - 1 - (int)blockIdx.x;   // tile id: c*64 + gy*8 + gx
    int c = bid >> 6, gy = (bid >> 3) & 7, gx = bid & 7;

    // zero 8KB
    {
        uint4 zz; zz.x = 0u; zz.y = 0u; zz.z = 0u; zz.w = 0u;
        ((uint4*)shw)[t] = zz;
        ((uint4*)shw)[256 + t] = zz;
    }
    __syncthreads();

    int wid = t >> 5, lane = t & 31;
    unsigned* myh = shw + (wid << 8);
    float c1b = p.c1b, c2b = p.c2b, c1c = p.c1c, c2c = p.c2c;
    float dhi = p.dhi;
    int win_lo = p.win_lo;
    int base = c * 262144 + (gy * 128) * 256 + gx * 32;   // float4 index of tile origin
    int g0 = base + (wid << 8) + lane;                    // this thread's first float4
    unsigned nib = 0u;                                    // 8 nibble counters (window bins)
    unsigned accA = 0u, accB = 0u;                        // u8-field accumulators (even/odd bins)
    // stride between iterations: 8 rows * 256 float4 = 2048

    float4 v0 = x[g0];
    float4 v1 = x[g0 + 1 * 2048];
    float4 v2 = x[g0 + 2 * 2048];
    float4 v3 = x[g0 + 3 * 2048];

#pragma unroll
    for (int it = 0; it < 16; it++) {
        float4 cur = v0; v0 = v1; v1 = v2; v2 = v3;
        if (it + 4 < 16) v3 = x[g0 + (it + 4) * 2048];
        float vals[4] = { cur.x, cur.y, cur.z, cur.w };
        int lbs[4];
#pragma unroll
        for (int j = 0; j < 4; j++) {
            float v = vals[j];
            float df = fminf(fmaf(v, c1b, c2b), dhi);   // lower clamp dropped (bias)
            int d = __float2int_rd(df);                 // window-relative bin (floor)
            lbs[j] = (int)fmaf(v, c1c, c2c);            // lookup bin (trunc; in [0,255])
            unsigned inc = __funnelshift_lc(0u, 1u, ((unsigned)d) << 2);
            nib += inc;
            if (inc == 0u) atomicAdd(&myh[d + win_lo], 1u);   // residue, rare
        }
        unsigned packed = __byte_perm(__byte_perm((unsigned)lbs[0], (unsigned)lbs[1], 0x0040),
                                      __byte_perm((unsigned)lbs[2], (unsigned)lbs[3], 0x0040),
                                      0x5410);
        g_bins[g0 + it * 2048] = packed;
        if (it & 1) {                                     // flush every 8 values
            accA += nib & 0x0F0F0F0Fu;                    // bins d = 0,2,4,6
            accB += (nib >> 4) & 0x0F0F0F0Fu;             // bins d = 1,3,5,7
            nib = 0u;
        }
    }

    // ---- merge register windows: unpack u8x4 -> u16x2 pairs, warp shfl-reduce
    unsigned pk0 =  accA        & 0x00FF00FFu;
    unsigned pk1 = (accA >> 8)  & 0x00FF00FFu;
    unsigned pk2 =  accB        & 0x00FF00FFu;
    unsigned pk3 = (accB >> 8)  & 0x00FF00FFu;
#pragma unroll
    for (int o = 16; o; o >>= 1) {
        pk0 += __shfl_down_sync(0xffffffffu, pk0, o);     // fields <= 2048, no carry
        pk1 += __shfl_down_sync(0xffffffffu, pk1, o);
        pk2 += __shfl_down_sync(0xffffffffu, pk2, o);
        pk3 += __shfl_down_sync(0xffffffffu, pk3, o);
    }
    if (lane == 0) {
        myh[win_lo + 0] = pk0 & 0xFFFFu;  myh[win_lo + 4] = pk0 >> 16;
        myh[win_lo + 2] = pk1 & 0xFFFFu;  myh[win_lo + 6] = pk1 >> 16;
        myh[win_lo + 1] = pk2 & 0xFFFFu;  myh[win_lo + 5] = pk2 >> 16;
        myh[win_lo + 3] = pk3 & 0xFFFFu;  myh[win_lo + 7] = pk3 >> 16;
    }
    __syncthreads();

    // reduce bin t across the 8 warp copies
    unsigned cnt = 0;
#pragma unroll
    for (int w = 0; w < 8; w++) cnt += shw[(w << 8) + t];

    // counts -> clip -> redistribute -> scan -> LUT   (all exact integer f32 math)
    float clipped = fminf((float)cnt, p.maxval);

    float s = clipped;
#pragma unroll
    for (int o = 16; o; o >>= 1) s += __shfl_down_sync(0xffffffffu, s, o);
    if (lane == 0) red[wid] = s;
    __syncthreads();
    if (t < 32) {
        float v2s = (t < 8) ? red[t] : 0.0f;
#pragma unroll
        for (int o = 4; o; o >>= 1) v2s += __shfl_down_sync(0xffffffffu, v2s, o);
        if (t == 0) red[32] = v2s;
    }
    __syncthreads();
    float total = red[32];
    int ex = TILE_PIXELS - (int)total;
    int residual = ex & (NBINS - 1);
    int redist = ex >> 8;
    float hv = clipped + (float)redist + ((t < residual) ? 1.0f : 0.0f);

    float vsc = hv;
#pragma unroll
    for (int o = 1; o < 32; o <<= 1) {
        float u = __shfl_up_sync(0xffffffffu, vsc, o);
        if (lane >= o) vsc += u;
    }
    if (lane == 31) red[wid] = vsc;
    __syncthreads();
    float off = 0.0f;
    for (int k = 0; k < wid; k++) off += red[k];
    vsc += off;

    float lutv = floorf(fminf(vsc * (255.0f / 16384.0f), 255.0f));
    g_lut[bid * NBINS + t] = lutv;
}

// ---------------------------------------------------------------- bf16-packed bilinear table
// Triggers programmatic launch completion at entry so k_out (PDL secondary)
// can start prefetching bins while this runs.
__global__ void __launch_bounds__(128) k_tbl() {
    cudaTriggerProgrammaticLaunchCompletion();
    Params p = g_par;
    if (!p.flag) return;
    int b = blockIdx.x >> 1;                   // slice = c*9 + ry
    int bin = ((blockIdx.x & 1) << 7) + threadIdx.x;
    int c = b / 9, ry = b % 9;
    int y0 = max(ry - 1, 0); int y1 = min(y0 + 1, 7);
    const float* L = g_lut + c * 64 * NBINS;
    float r0[8], r1[8];
#pragma unroll
    for (int xx = 0; xx < 8; xx++) r0[xx] = L[(y0 * 8 + xx) * NBINS + bin];
#pragma unroll
    for (int xx = 0; xx < 8; xx++) r1[xx] = L[(y1 * 8 + xx) * NBINS + bin];
#pragma unroll
    for (int rx = 0; rx < 9; rx++) {
        int x0 = max(rx - 1, 0); int x1 = min(x0 + 1, 7);
        float a0 = r0[x0], b0 = r0[x1] - r0[x0];
        float a1 = r1[x0], b1 = r1[x1] - r1[x0];
        uint2 e;
        e.x = (__float_as_uint(b0) & 0xFFFF0000u) | (__float_as_uint(a0) >> 16);
        e.y = (__float_as_uint(b1) & 0xFFFF0000u) | (__float_as_uint(a1) >> 16);
        g_tblq[(b * 9 + rx) * NBINS + bin] = e;
    }
}

// ---------------------------------------------------------------- output: ONE 8B gather + interp + log2
// PDL secondary: launches while k_tbl runs. Bins (written by hist, which is
// guaranteed complete) are prefetched BEFORE the grid-dependency sync; only
// the g_tblq gathers wait for k_tbl.
__global__ void __launch_bounds__(256) k_out(const float4* __restrict__ x,
                                             float4* __restrict__ out, int n4) {
    Params p = g_par;
    int t = threadIdx.x;
    int i0 = blockIdx.x * 2048;
    int base = i0 + t;
    if (p.flag) {
        unsigned bp[8];
#pragma unroll
        for (int k = 0; k < 8; k++) bp[k] = __ldcs(&g_bins[base + k * 256]);
        int c  = i0 >> 18;
        int h0 = (i0 & 262143) >> 8;
        int w4 = t << 2;
        int rx = (w4 + 64) >> 7;
        float wx[4];
        wx[0] = fmaf((float)w4, 0.0078125f, 0.50390625f - (float)rx);
        wx[1] = wx[0] + 0.0078125f;
        wx[2] = wx[0] + 0.015625f;
        wx[3] = wx[0] + 0.0234375f;
        const uint2* tbc = g_tblq + (c * 81 + rx) * NBINS;
        cudaGridDependencySynchronize();          // wait for k_tbl's table
#pragma unroll
        for (int k = 0; k < 8; k++) {
            int h  = h0 + k;
            int ry = (h + 64) >> 7;
            float wy = fmaf((float)h, 0.0078125f, 0.50390625f - (float)ry);
            const uint2* tb = tbc + ry * 9 * NBINS;
            float o[4];
#pragma unroll
            for (int j = 0; j < 4; j++) {
                unsigned bin = __byte_perm(bp[k], 0u, 0x4440u + (unsigned)j);
                uint2 e = tb[bin];
                float a0 = __uint_as_float(e.x << 16);
                float b0 = __uint_as_float(e.x & 0xFFFF0000u);
                float a1 = __uint_as_float(e.y << 16);
                float b1 = __uint_as_float(e.y & 0xFFFF0000u);
                float top = fmaf(wx[j], b0, a0);
                float bot = fmaf(wx[j], b1, a1);
                float itp = fmaf(wy, bot - top, top);
                float val = fmaf(itp, (1.0f / 255.0f), 1.0f);
                o[j] = __log2f(val);
            }
            float4 ov; ov.x = o[0]; ov.y = o[1]; ov.z = o[2]; ov.w = o[3];
            __stcs(&out[base + k * 256], ov);
        }
    } else {
        cudaGridDependencySynchronize();
#pragma unroll
        for (int k = 0; k < 8; k++) {
            int i = base + k * 256;
            if (i < n4) {
                float4 v = x[i];
                float4 ov;
                ov.x = log2f(1.0f + fmaf(v.x, p.c1, p.c2));
                ov.y = log2f(1.0f + fmaf(v.y, p.c1, p.c2));
                ov.z = log2f(1.0f + fmaf(v.z, p.c1, p.c2));
                ov.w = log2f(1.0f + fmaf(v.w, p.c1, p.c2));
                __stcs(&out[i], ov);
            }
        }
    }
}

// ---------------------------------------------------------------- launch
extern "C" void kernel_launch(void* const* d_in, const int* in_sizes, int n_in,
                              void* d_out, int out_size) {
    (void)n_in; (void)out_size;
    const float* x = (const float*)d_in[0];
    int n   = in_sizes[0];          // 32 * 1024 * 1024
    int C   = n >> 20;
    int n16 = n >> 4;
    int n4  = n >> 2;

    k_reduce<<<NPART, 256>>>((const float4*)x, n16);
    k_finalize<<<1, 256>>>(n);
    k_hist_lut<<<C * 64, 256>>>((const float4*)x);
    k_tbl<<<C * 9 * 2, 128>>>();

    // k_out as PDL secondary of k_tbl
    cudaLaunchConfig_t cfg = {};
    cfg.gridDim  = dim3((unsigned)(n4 / 2048), 1, 1);
    cfg.blockDim = dim3(256, 1, 1);
    cudaLaunchAttribute attrs[1];
    attrs[0].id = cudaLaunchAttributeProgrammaticStreamSerialization;
    attrs[0].val.programmaticStreamSerializationAllowed = 1;
    cfg.attrs = attrs;
    cfg.numAttrs = 1;
    cudaLaunchKernelEx(&cfg, k_out, (const float4*)x, (float4*)d_out, n4);
}